// round 4
// baseline (speedup 1.0000x reference)
#include <cuda_runtime.h>
#include <math.h>

#define B_   4
#define H_   64
#define W_   128
#define DM_  256
#define NH_  8
#define K_   4
#define SC_  2
#define DK_  32
#define NPIX (B_*H_*W_)      // 32768
#define NOA  192             // 128 offset cols + 64 attn cols

// ------------------------- scratch (device globals; no allocation) -------------------------
__device__ __align__(256) float g_q   [NPIX*DM_];
__device__ __align__(256) float g_sf0 [NPIX*DM_];
__device__ __align__(256) float g_sf1 [NPIX*DM_];
__device__ __align__(256) float g_offA[NPIX*NOA];
__device__ __align__(256) float g_feat[NPIX*DM_];
__device__ __align__(256) float g_Wcat[DM_*NOA];
__device__ __align__(256) float g_bcat[NOA];

// ------------------------- concat Wo|Wa and bo|ba -------------------------
__global__ void concat_wa(const float* __restrict__ Wo, const float* __restrict__ bo,
                          const float* __restrict__ Wa, const float* __restrict__ ba)
{
    int i = blockIdx.x * blockDim.x + threadIdx.x;
    const int total = DM_ * NOA;
    if (i < total) {
        int r = i / NOA, c = i - r * NOA;
        g_Wcat[i] = (c < 128) ? Wo[r * 128 + c] : Wa[r * 64 + (c - 128)];
    }
    if (i < NOA) g_bcat[i] = (i < 128) ? bo[i] : ba[i - 128];
}

// ------------------------- tiled SGEMM with bias: C[M,N] = A[M,K] @ B[K,N] + bias ----------
// BM=128, BN=64, BK=16, 256 threads, 8x4 register tile. Requires M%128==0, N%64==0, K%16==0.
__global__ __launch_bounds__(256)
void sgemm_bias(const float* __restrict__ A, const float* __restrict__ Bm,
                const float* __restrict__ bias, float* __restrict__ C,
                int N, int K)
{
    const int BM = 128, BN = 64, BK = 16;
    __shared__ float As[BK][BM + 4];   // transposed A tile (+pad to soften store conflicts)
    __shared__ float Bs[BK][BN];

    const int tid = threadIdx.x;
    const int rowBase = blockIdx.y * BM;
    const int colBase = blockIdx.x * BN;
    const int tx = tid & 15;          // 16 cols of threads -> 4 output cols each
    const int ty = tid >> 4;          // 16 rows of threads -> 8 output rows each

    float acc[8][4];
#pragma unroll
    for (int i = 0; i < 8; i++)
#pragma unroll
        for (int j = 0; j < 4; j++) acc[i][j] = 0.f;

    for (int k0 = 0; k0 < K; k0 += BK) {
        // load A tile 128x16 (2 float4 per thread), store transposed
#pragma unroll
        for (int it = 0; it < 2; it++) {
            int idx = tid + it * 256;          // 0..511
            int r = idx >> 2;                  // 0..127
            int c4 = idx & 3;                  // float4 slot within the 16-wide row
            float4 v = *(const float4*)(A + (size_t)(rowBase + r) * K + k0 + c4 * 4);
            As[c4 * 4 + 0][r] = v.x;
            As[c4 * 4 + 1][r] = v.y;
            As[c4 * 4 + 2][r] = v.z;
            As[c4 * 4 + 3][r] = v.w;
        }
        // load B tile 16x64 (1 float4 per thread)
        {
            int r = tid >> 4;                  // 0..15
            int c4 = tid & 15;                 // 0..15
            float4 v = *(const float4*)(Bm + (size_t)(k0 + r) * N + colBase + c4 * 4);
            *(float4*)(&Bs[r][c4 * 4]) = v;
        }
        __syncthreads();

#pragma unroll
        for (int kk = 0; kk < BK; kk++) {
            float4 b4 = *(const float4*)(&Bs[kk][tx * 4]);
            float a[8];
#pragma unroll
            for (int i = 0; i < 8; i++) a[i] = As[kk][ty * 8 + i];
#pragma unroll
            for (int i = 0; i < 8; i++) {
                acc[i][0] += a[i] * b4.x;
                acc[i][1] += a[i] * b4.y;
                acc[i][2] += a[i] * b4.z;
                acc[i][3] += a[i] * b4.w;
            }
        }
        __syncthreads();
    }

    float4 bia = *(const float4*)(bias + colBase + tx * 4);
#pragma unroll
    for (int i = 0; i < 8; i++) {
        float4 o;
        o.x = acc[i][0] + bia.x;
        o.y = acc[i][1] + bia.y;
        o.z = acc[i][2] + bia.z;
        o.w = acc[i][3] + bia.w;
        *(float4*)(C + (size_t)(rowBase + ty * 8 + i) * N + colBase + tx * 4) = o;
    }
}

// ------------------------- deformable sampling + softmax + aggregate -----------------------
// 1 block per pixel, 8 warps = 8 heads, lane = channel d (0..31).
__global__ __launch_bounds__(256)
void sample_kernel(const float* __restrict__ refp)
{
    const int pixel = blockIdx.x;                 // 0..NPIX-1
    const int b = pixel / (H_ * W_);
    const int rem = pixel - b * (H_ * W_);        // y*W + x
    const int h = threadIdx.x >> 5;
    const int d = threadIdx.x & 31;

    // torch .repeat quirk: ref for bh-index n = b*NH+h is ref_point[n % B]
    const int rb = (b * NH_ + h) % B_;
    const int refIdx = (rb * (H_ * W_) + rem) * 2;
    const float ry = refp[refIdx + 0];
    const float rx = refp[refIdx + 1];

    // softmax over the 8 (scale, point) logits for this head
    const float* Arow = g_offA + (size_t)pixel * NOA + 128 + h * 8;
    float lg[8];
    float mx = -1e30f;
#pragma unroll
    for (int j = 0; j < 8; j++) { lg[j] = Arow[j]; mx = fmaxf(mx, lg[j]); }
    float ssum = 0.f;
#pragma unroll
    for (int j = 0; j < 8; j++) { lg[j] = expf(lg[j] - mx); ssum += lg[j]; }
    const float inv = 1.f / ssum;

    const float* offrow = g_offA + (size_t)pixel * NOA + h * 16;

    const float sy = (float)H_ / (float)(H_ - 1);
    const float sx = (float)W_ / (float)(W_ - 1);

    float acc = 0.f;
#pragma unroll
    for (int l = 0; l < 2; l++) {
        const float* sf = l ? g_sf1 : g_sf0;
        const float* sfb = sf + (size_t)b * (H_ * W_) * DM_ + h * DK_ + d;
#pragma unroll
        for (int k = 0; k < 4; k++) {
            const float py = (ry + offrow[l * 8 + k * 2 + 0]) * sy - 0.5f;
            const float px = (rx + offrow[l * 8 + k * 2 + 1]) * sx - 0.5f;
            const float w  = lg[l * 4 + k] * inv;

            const float fy = floorf(py), fx = floorf(px);
            const int y0 = (int)fy, x0 = (int)fx;
            const float wy1 = py - fy, wx1 = px - fx;
            const float wy0 = 1.f - wy1, wx0 = 1.f - wx1;

            const bool yv0 = (y0 >= 0) && (y0 < H_);
            const bool yv1 = (y0 + 1 >= 0) && (y0 + 1 < H_);
            const bool xv0 = (x0 >= 0) && (x0 < W_);
            const bool xv1 = (x0 + 1 >= 0) && (x0 + 1 < W_);

            float v00 = 0.f, v01 = 0.f, v10 = 0.f, v11 = 0.f;
            if (yv0 && xv0) v00 = sfb[(size_t)(y0 * W_ + x0) * DM_];
            if (yv0 && xv1) v01 = sfb[(size_t)(y0 * W_ + x0 + 1) * DM_];
            if (yv1 && xv0) v10 = sfb[(size_t)((y0 + 1) * W_ + x0) * DM_];
            if (yv1 && xv1) v11 = sfb[(size_t)((y0 + 1) * W_ + x0 + 1) * DM_];

            acc += w * (wy0 * (wx0 * v00 + wx1 * v01) + wy1 * (wx0 * v10 + wx1 * v11));
        }
    }
    g_feat[(size_t)pixel * DM_ + h * DK_ + d] = acc;
}

// ------------------------- launch -------------------------
extern "C" void kernel_launch(void* const* d_in, const int* in_sizes, int n_in,
                              void* d_out, int out_size)
{
    const float* query = (const float*)d_in[0];
    const float* keys0 = (const float*)d_in[1];
    const float* keys1 = (const float*)d_in[2];
    const float* refp  = (const float*)d_in[3];
    const float* Wq = (const float*)d_in[4];
    const float* bq = (const float*)d_in[5];
    const float* Wk = (const float*)d_in[6];
    const float* bk = (const float*)d_in[7];
    const float* Wo = (const float*)d_in[8];
    const float* bo = (const float*)d_in[9];
    const float* Wa = (const float*)d_in[10];
    const float* ba = (const float*)d_in[11];
    const float* Wm = (const float*)d_in[12];
    const float* bm = (const float*)d_in[13];
    float* out = (float*)d_out;

    float *q, *sf0, *sf1, *offA, *feat, *Wcat, *bcat;
    cudaGetSymbolAddress((void**)&q,    g_q);
    cudaGetSymbolAddress((void**)&sf0,  g_sf0);
    cudaGetSymbolAddress((void**)&sf1,  g_sf1);
    cudaGetSymbolAddress((void**)&offA, g_offA);
    cudaGetSymbolAddress((void**)&feat, g_feat);
    cudaGetSymbolAddress((void**)&Wcat, g_Wcat);
    cudaGetSymbolAddress((void**)&bcat, g_bcat);

    concat_wa<<<(DM_ * NOA + 255) / 256, 256>>>(Wo, bo, Wa, ba);

    dim3 gFull(DM_ / 64, NPIX / 128);            // (4, 256)
    sgemm_bias<<<gFull, 256>>>(query, Wq, bq, q,   DM_, DM_);
    sgemm_bias<<<gFull, 256>>>(keys0, Wk, bk, sf0, DM_, DM_);
    sgemm_bias<<<gFull, 256>>>(keys1, Wk, bk, sf1, DM_, DM_);

    dim3 gOA(NOA / 64, NPIX / 128);              // (3, 256)
    sgemm_bias<<<gOA, 256>>>(q, Wcat, bcat, offA, NOA, DM_);

    sample_kernel<<<NPIX, 256>>>(refp);

    sgemm_bias<<<gFull, 256>>>(feat, Wm, bm, out, DM_, DM_);

    (void)in_sizes; (void)n_in; (void)out_size;
}

// round 6
// speedup vs baseline: 2.0363x; 2.0363x over previous
#include <cuda_runtime.h>
#include <cstdint>
#include <math.h>

#define B_   4
#define H_   64
#define W_   128
#define DM_  256
#define NH_  8
#define K_   4
#define SC_  2
#define DK_  32
#define NPIX (B_*H_*W_)      // 32768
#define NOAP 256             // padded offA width (128 off + 64 attn + 64 pad)

// ------------------------- scratch (device globals; no allocation) -------------------------
__device__ __align__(256) float g_sf0 [NPIX*DM_];
__device__ __align__(256) float g_sf1 [NPIX*DM_];
__device__ __align__(256) float g_offA[NPIX*NOAP];
__device__ __align__(256) float g_feat[NPIX*DM_];
__device__ __align__(256) float g_Weff[DM_*NOAP];
__device__ __align__(256) float g_beff[NOAP];

// ------------------------- Weff = Wq @ [Wo | Wa | 0],  beff = bq @ Wcat + [bo|ba|0] --------
__global__ void weff_kernel(const float* __restrict__ Wq, const float* __restrict__ Wo,
                            const float* __restrict__ Wa)
{
    __shared__ float wq[DM_];
    const int r = blockIdx.x;
    const int c = threadIdx.x;
    wq[c] = Wq[r * DM_ + c];
    __syncthreads();
    float acc = 0.f;
    if (c < 128) {
        for (int k = 0; k < DM_; k++) acc += wq[k] * Wo[k * 128 + c];
    } else if (c < 192) {
        const int cc = c - 128;
        for (int k = 0; k < DM_; k++) acc += wq[k] * Wa[k * 64 + cc];
    }
    g_Weff[r * NOAP + c] = (c < 192) ? acc : 0.f;
}

__global__ void beff_kernel(const float* __restrict__ bq, const float* __restrict__ Wo,
                            const float* __restrict__ Wa, const float* __restrict__ bo,
                            const float* __restrict__ ba)
{
    const int c = threadIdx.x;
    float acc = 0.f;
    if (c < 128) {
        for (int k = 0; k < DM_; k++) acc += bq[k] * Wo[k * 128 + c];
        acc += bo[c];
    } else if (c < 192) {
        const int cc = c - 128;
        for (int k = 0; k < DM_; k++) acc += bq[k] * Wa[k * 64 + cc];
        acc += ba[cc];
    }
    g_beff[c] = (c < 192) ? acc : 0.f;
}

// ------------------------- TF32 tensor-core GEMM: C[M,256] = A[M,256] @ B[256,256] + bias --
// CTA tile 128x128x32, 8 warps (4m x 2n), warp tile 32x64 = 2x8 m16n8k8 mma tiles.
// Register-staged double buffering; cvt.rna at staging; conflict-free fragment LDS.

__device__ __forceinline__ unsigned f2tf(float f) {
    unsigned u;
    asm("cvt.rna.tf32.f32 %0, %1;" : "=r"(u) : "f"(f));
    return u;
}

__device__ __forceinline__ void mma_tf32(float c[4], const unsigned a[4], const unsigned b[2]) {
    asm volatile(
        "mma.sync.aligned.m16n8k8.row.col.f32.tf32.tf32.f32 "
        "{%0,%1,%2,%3}, {%4,%5,%6,%7}, {%8,%9}, {%0,%1,%2,%3};"
        : "+f"(c[0]), "+f"(c[1]), "+f"(c[2]), "+f"(c[3])
        : "r"(a[0]), "r"(a[1]), "r"(a[2]), "r"(a[3]), "r"(b[0]), "r"(b[1]));
}

#define KDIM 256
#define NDIM 256
#define BK   32

__global__ __launch_bounds__(256)
void gemm_tf32(const float* __restrict__ A, const float* __restrict__ Bm,
               const float* __restrict__ bias, float* __restrict__ C)
{
    __shared__ unsigned As[128][36];   // row-major [m][k], stride 36: frag bank = lane (cf-free)
    __shared__ unsigned Bs[32][136];   // [k][n], stride 136: frag bank = 8*tg+g (cf-free)

    const int tid  = threadIdx.x;
    const int lane = tid & 31;
    const int wid  = tid >> 5;
    const int g    = lane >> 2;        // groupID
    const int tg   = lane & 3;         // threadID_in_group
    const int warpRow = (wid & 3) * 32;
    const int warpCol = (wid >> 2) * 64;
    const int rowBase = blockIdx.y * 128;
    const int colBase = blockIdx.x * 128;

    // staging coordinates
    const int am  = tid >> 3;          // 0..31  (+32*i)
    const int akc = (tid & 7) * 4;     // k col chunk
    const int bk  = tid >> 5;          // 0..7   (+8*i)
    const int bnc = (tid & 31) * 4;    // n col chunk

    const float* Ap = A + (size_t)rowBase * KDIM;
    const float* Bp = Bm + colBase;

    float4 ra[4], rb[4];

#define GLOAD(kt)                                                                   \
    {                                                                               \
        _Pragma("unroll")                                                           \
        for (int i = 0; i < 4; i++)                                                 \
            ra[i] = *(const float4*)(Ap + (size_t)(am + 32 * i) * KDIM + (kt) * BK + akc); \
        _Pragma("unroll")                                                           \
        for (int i = 0; i < 4; i++)                                                 \
            rb[i] = *(const float4*)(Bp + (size_t)((kt) * BK + bk + 8 * i) * NDIM + bnc);  \
    }

#define SSTORE()                                                                    \
    {                                                                               \
        _Pragma("unroll")                                                           \
        for (int i = 0; i < 4; i++) {                                               \
            uint4 u = make_uint4(f2tf(ra[i].x), f2tf(ra[i].y), f2tf(ra[i].z), f2tf(ra[i].w)); \
            *(uint4*)(&As[am + 32 * i][akc]) = u;                                   \
        }                                                                           \
        _Pragma("unroll")                                                           \
        for (int i = 0; i < 4; i++) {                                               \
            uint4 u = make_uint4(f2tf(rb[i].x), f2tf(rb[i].y), f2tf(rb[i].z), f2tf(rb[i].w)); \
            *(uint4*)(&Bs[bk + 8 * i][bnc]) = u;                                    \
        }                                                                           \
    }

    float acc[2][8][4];
#pragma unroll
    for (int mt = 0; mt < 2; mt++)
#pragma unroll
        for (int nt = 0; nt < 8; nt++)
#pragma unroll
            for (int j = 0; j < 4; j++) acc[mt][nt][j] = 0.f;

    GLOAD(0);
    SSTORE();
    __syncthreads();

    const int TILES = KDIM / BK;   // 8
    for (int kt = 0; kt < TILES; kt++) {
        if (kt < TILES - 1) GLOAD(kt + 1);

#pragma unroll
        for (int s = 0; s < 4; s++) {
            const int k0 = s * 8;
            unsigned af[2][4];
#pragma unroll
            for (int mt = 0; mt < 2; mt++) {
                const int r0 = warpRow + mt * 16 + g;
                af[mt][0] = As[r0][k0 + tg];
                af[mt][1] = As[r0 + 8][k0 + tg];
                af[mt][2] = As[r0][k0 + tg + 4];
                af[mt][3] = As[r0 + 8][k0 + tg + 4];
            }
            unsigned bf[8][2];
#pragma unroll
            for (int nt = 0; nt < 8; nt++) {
                const int c0 = warpCol + nt * 8 + g;
                bf[nt][0] = Bs[k0 + tg][c0];
                bf[nt][1] = Bs[k0 + tg + 4][c0];
            }
#pragma unroll
            for (int mt = 0; mt < 2; mt++)
#pragma unroll
                for (int nt = 0; nt < 8; nt++)
                    mma_tf32(acc[mt][nt], af[mt], bf[nt]);
        }
        __syncthreads();
        if (kt < TILES - 1) {
            SSTORE();
            __syncthreads();
        }
    }

    // epilogue: bias + store (c0,c1 contiguous -> float2)
#pragma unroll
    for (int mt = 0; mt < 2; mt++) {
        const int row = rowBase + warpRow + mt * 16 + g;
#pragma unroll
        for (int nt = 0; nt < 8; nt++) {
            const int col = colBase + warpCol + nt * 8 + tg * 2;
            const float2 bv = *(const float2*)(bias + col);
            float2 o0, o1;
            o0.x = acc[mt][nt][0] + bv.x;
            o0.y = acc[mt][nt][1] + bv.y;
            o1.x = acc[mt][nt][2] + bv.x;
            o1.y = acc[mt][nt][3] + bv.y;
            *(float2*)(C + (size_t)row * NDIM + col) = o0;
            *(float2*)(C + (size_t)(row + 8) * NDIM + col) = o1;
        }
    }
#undef GLOAD
#undef SSTORE
}

// ------------------------- deformable sampling + softmax + aggregate -----------------------
// 1 block per pixel, 8 warps = 8 heads, lane = channel d (0..31).
__global__ __launch_bounds__(256)
void sample_kernel(const float* __restrict__ refp)
{
    const int pixel = blockIdx.x;
    const int b = pixel / (H_ * W_);
    const int rem = pixel - b * (H_ * W_);
    const int h = threadIdx.x >> 5;
    const int d = threadIdx.x & 31;

    // torch .repeat quirk: ref for bh-index n = b*NH+h is ref_point[n % B]
    const int rb = (b * NH_ + h) % B_;
    const int refIdx = (rb * (H_ * W_) + rem) * 2;
    const float ry = refp[refIdx + 0];
    const float rx = refp[refIdx + 1];

    const float* Arow = g_offA + (size_t)pixel * NOAP + 128 + h * 8;
    float lg[8];
    float mx = -1e30f;
#pragma unroll
    for (int j = 0; j < 8; j++) { lg[j] = Arow[j]; mx = fmaxf(mx, lg[j]); }
    float ssum = 0.f;
#pragma unroll
    for (int j = 0; j < 8; j++) { lg[j] = expf(lg[j] - mx); ssum += lg[j]; }
    const float inv = 1.f / ssum;

    const float* offrow = g_offA + (size_t)pixel * NOAP + h * 16;

    const float sy = (float)H_ / (float)(H_ - 1);
    const float sx = (float)W_ / (float)(W_ - 1);

    float acc = 0.f;
#pragma unroll
    for (int l = 0; l < 2; l++) {
        const float* sf = l ? g_sf1 : g_sf0;
        const float* sfb = sf + (size_t)b * (H_ * W_) * DM_ + h * DK_ + d;
#pragma unroll
        for (int k = 0; k < 4; k++) {
            const float py = (ry + offrow[l * 8 + k * 2 + 0]) * sy - 0.5f;
            const float px = (rx + offrow[l * 8 + k * 2 + 1]) * sx - 0.5f;
            const float w  = lg[l * 4 + k] * inv;

            const float fy = floorf(py), fx = floorf(px);
            const int y0 = (int)fy, x0 = (int)fx;
            const float wy1 = py - fy, wx1 = px - fx;
            const float wy0 = 1.f - wy1, wx0 = 1.f - wx1;

            const bool yv0 = (y0 >= 0) && (y0 < H_);
            const bool yv1 = (y0 + 1 >= 0) && (y0 + 1 < H_);
            const bool xv0 = (x0 >= 0) && (x0 < W_);
            const bool xv1 = (x0 + 1 >= 0) && (x0 + 1 < W_);

            float v00 = 0.f, v01 = 0.f, v10 = 0.f, v11 = 0.f;
            if (yv0 && xv0) v00 = sfb[(size_t)(y0 * W_ + x0) * DM_];
            if (yv0 && xv1) v01 = sfb[(size_t)(y0 * W_ + x0 + 1) * DM_];
            if (yv1 && xv0) v10 = sfb[(size_t)((y0 + 1) * W_ + x0) * DM_];
            if (yv1 && xv1) v11 = sfb[(size_t)((y0 + 1) * W_ + x0 + 1) * DM_];

            acc += w * (wy0 * (wx0 * v00 + wx1 * v01) + wy1 * (wx0 * v10 + wx1 * v11));
        }
    }
    g_feat[(size_t)pixel * DM_ + h * DK_ + d] = acc;
}

// ------------------------- launch -------------------------
extern "C" void kernel_launch(void* const* d_in, const int* in_sizes, int n_in,
                              void* d_out, int out_size)
{
    const float* query = (const float*)d_in[0];
    const float* keys0 = (const float*)d_in[1];
    const float* keys1 = (const float*)d_in[2];
    const float* refp  = (const float*)d_in[3];
    const float* Wq = (const float*)d_in[4];
    const float* bq = (const float*)d_in[5];
    const float* Wk = (const float*)d_in[6];
    const float* bk = (const float*)d_in[7];
    const float* Wo = (const float*)d_in[8];
    const float* bo = (const float*)d_in[9];
    const float* Wa = (const float*)d_in[10];
    const float* ba = (const float*)d_in[11];
    const float* Wm = (const float*)d_in[12];
    const float* bm = (const float*)d_in[13];
    float* out = (float*)d_out;

    float *sf0, *sf1, *offA, *feat, *Weff, *beff;
    cudaGetSymbolAddress((void**)&sf0,  g_sf0);
    cudaGetSymbolAddress((void**)&sf1,  g_sf1);
    cudaGetSymbolAddress((void**)&offA, g_offA);
    cudaGetSymbolAddress((void**)&feat, g_feat);
    cudaGetSymbolAddress((void**)&Weff, g_Weff);
    cudaGetSymbolAddress((void**)&beff, g_beff);

    weff_kernel<<<DM_, 256>>>(Wq, Wo, Wa);
    beff_kernel<<<1, 256>>>(bq, Wo, Wa, bo, ba);

    dim3 gg(NDIM / 128, NPIX / 128);   // (2, 256)
    gemm_tf32<<<gg, 256>>>(query, Weff, beff, offA);
    gemm_tf32<<<gg, 256>>>(keys0, Wk, bk, sf0);
    gemm_tf32<<<gg, 256>>>(keys1, Wk, bk, sf1);

    sample_kernel<<<NPIX, 256>>>(refp);

    gemm_tf32<<<gg, 256>>>(feat, Wm, bm, out);

    (void)in_sizes; (void)n_in; (void)out_size;
}

// round 7
// speedup vs baseline: 2.1273x; 1.0447x over previous
#include <cuda_runtime.h>
#include <cuda_fp16.h>
#include <cstdint>
#include <math.h>

#define B_   4
#define H_   64
#define W_   128
#define DM_  256
#define NH_  8
#define NPIX (B_*H_*W_)      // 32768
#define NOAP 256             // padded offA width (128 off + 64 attn + 64 pad)
#define KDIM 256
#define NDIM 256

// ------------------------- scratch (device globals; no allocation) -------------------------
__device__ __align__(256) __half g_sf0h [NPIX*DM_];
__device__ __align__(256) __half g_sf1h [NPIX*DM_];
__device__ __align__(256) __half g_feath[NPIX*DM_];
__device__ __align__(256) float  g_offA [NPIX*NOAP];
__device__ __align__(256) float  g_Weff [DM_*NOAP];
__device__ __align__(256) float  g_beff [NOAP];

// ------------------------- Weff = Wq @ [Wo | Wa | 0],  beff = bq @ Wcat + [bo|ba|0] --------
__global__ void weff_kernel(const float* __restrict__ Wq, const float* __restrict__ Wo,
                            const float* __restrict__ Wa)
{
    __shared__ float wq[DM_];
    const int r = blockIdx.x;
    const int c = threadIdx.x;
    wq[c] = Wq[r * DM_ + c];
    __syncthreads();
    float acc = 0.f;
    if (c < 128) {
        for (int k = 0; k < DM_; k++) acc += wq[k] * Wo[k * 128 + c];
    } else if (c < 192) {
        const int cc = c - 128;
        for (int k = 0; k < DM_; k++) acc += wq[k] * Wa[k * 64 + cc];
    }
    g_Weff[r * NOAP + c] = (c < 192) ? acc : 0.f;
}

__global__ void beff_kernel(const float* __restrict__ bq, const float* __restrict__ Wo,
                            const float* __restrict__ Wa, const float* __restrict__ bo,
                            const float* __restrict__ ba)
{
    const int c = threadIdx.x;
    float acc = 0.f;
    if (c < 128) {
        for (int k = 0; k < DM_; k++) acc += bq[k] * Wo[k * 128 + c];
        acc += bo[c];
    } else if (c < 192) {
        const int cc = c - 128;
        for (int k = 0; k < DM_; k++) acc += bq[k] * Wa[k * 64 + cc];
        acc += ba[cc];
    }
    g_beff[c] = (c < 192) ? acc : 0.f;
}

// ------------------------- FP16 tensor-core GEMM: C[M,256] = A[M,256] @ B[256,256] + bias --
// CTA tile 128x128x32, 8 warps (4m x 2n), warp tile 32x64 = 2x8 m16n8k16 mma tiles.
// Register-staged double buffering; fp32->fp16 rn at staging; conflict-free fragment LDS.

__device__ __forceinline__ unsigned pack2(float x, float y) {
    __half2 h = __floats2half2_rn(x, y);
    return *reinterpret_cast<unsigned*>(&h);
}

template<typename T>
__device__ __forceinline__ uint2 loadA4(const T* p);
template<>
__device__ __forceinline__ uint2 loadA4<float>(const float* p) {
    float4 v = *(const float4*)p;
    return make_uint2(pack2(v.x, v.y), pack2(v.z, v.w));
}
template<>
__device__ __forceinline__ uint2 loadA4<__half>(const __half* p) {
    return *(const uint2*)p;
}

template<typename T>
__device__ __forceinline__ void storeC2(T* C, size_t idx, float v0, float v1);
template<>
__device__ __forceinline__ void storeC2<float>(float* C, size_t idx, float v0, float v1) {
    *(float2*)(C + idx) = make_float2(v0, v1);
}
template<>
__device__ __forceinline__ void storeC2<__half>(__half* C, size_t idx, float v0, float v1) {
    *(unsigned*)(C + idx) = pack2(v0, v1);
}

__device__ __forceinline__ void mma_f16(float c[4], const unsigned a[4], const unsigned b[2]) {
    asm volatile(
        "mma.sync.aligned.m16n8k16.row.col.f32.f16.f16.f32 "
        "{%0,%1,%2,%3}, {%4,%5,%6,%7}, {%8,%9}, {%0,%1,%2,%3};"
        : "+f"(c[0]), "+f"(c[1]), "+f"(c[2]), "+f"(c[3])
        : "r"(a[0]), "r"(a[1]), "r"(a[2]), "r"(a[3]), "r"(b[0]), "r"(b[1]));
}

template<typename TIN, typename TOUT>
__global__ __launch_bounds__(256)
void gemm_f16(const TIN* __restrict__ A, const float* __restrict__ Bm,
              const float* __restrict__ bias, TOUT* __restrict__ C)
{
    // As2[m][c]: half2 = A[m][2c..2c+1]; stride 20 -> frag banks (20g+tg)%32 bijective
    __shared__ unsigned As2[128][20];
    // Bs2[p][n]: half2 = B[2p..2p+1][n]; stride 136 -> frag banks (8tg+g)%32 bijective
    __shared__ unsigned Bs2[16][136];

    const int tid  = threadIdx.x;
    const int lane = tid & 31;
    const int wid  = tid >> 5;
    const int g    = lane >> 2;
    const int tg   = lane & 3;
    const int warpRow = (wid & 3) * 32;
    const int warpCol = (wid >> 2) * 64;
    const int rowBase = blockIdx.y * 128;
    const int colBase = blockIdx.x * 128;

    // staging coordinates
    const int am  = tid >> 3;          // A row 0..31 (+32*i)
    const int akc = (tid & 7) * 4;     // A k element offset (4 elems)
    const int bp  = tid >> 5;          // B k-pair 0..7 (+8)
    const int bnc = (tid & 31) * 4;    // B n col chunk

    const TIN*   Ap = A + (size_t)rowBase * KDIM;
    const float* Bp = Bm + colBase;

    uint2  ra[4];
    float4 rbf[4];

#define GLOAD(kt)                                                                       \
    {                                                                                   \
        _Pragma("unroll")                                                               \
        for (int i = 0; i < 4; i++)                                                     \
            ra[i] = loadA4<TIN>(Ap + (size_t)(am + 32 * i) * KDIM + (kt) * 32 + akc);   \
        rbf[0] = *(const float4*)(Bp + (size_t)((kt) * 32 + 2 * bp     ) * NDIM + bnc); \
        rbf[1] = *(const float4*)(Bp + (size_t)((kt) * 32 + 2 * bp +  1) * NDIM + bnc); \
        rbf[2] = *(const float4*)(Bp + (size_t)((kt) * 32 + 2 * bp + 16) * NDIM + bnc); \
        rbf[3] = *(const float4*)(Bp + (size_t)((kt) * 32 + 2 * bp + 17) * NDIM + bnc); \
    }

#define SSTORE()                                                                        \
    {                                                                                   \
        _Pragma("unroll")                                                               \
        for (int i = 0; i < 4; i++)                                                     \
            *(uint2*)(&As2[am + 32 * i][(tid & 7) * 2]) = ra[i];                        \
        *(uint4*)(&Bs2[bp][bnc]) = make_uint4(                                          \
            pack2(rbf[0].x, rbf[1].x), pack2(rbf[0].y, rbf[1].y),                       \
            pack2(rbf[0].z, rbf[1].z), pack2(rbf[0].w, rbf[1].w));                      \
        *(uint4*)(&Bs2[bp + 8][bnc]) = make_uint4(                                      \
            pack2(rbf[2].x, rbf[3].x), pack2(rbf[2].y, rbf[3].y),                       \
            pack2(rbf[2].z, rbf[3].z), pack2(rbf[2].w, rbf[3].w));                      \
    }

    float acc[2][8][4];
#pragma unroll
    for (int mt = 0; mt < 2; mt++)
#pragma unroll
        for (int nt = 0; nt < 8; nt++)
#pragma unroll
            for (int j = 0; j < 4; j++) acc[mt][nt][j] = 0.f;

    GLOAD(0);
    SSTORE();
    __syncthreads();

    const int TILES = KDIM / 32;   // 8
    for (int kt = 0; kt < TILES; kt++) {
        if (kt < TILES - 1) GLOAD(kt + 1);

#pragma unroll
        for (int s = 0; s < 2; s++) {
            const int kc0 = s * 8;     // half2-pair base within tile
            unsigned af[2][4];
#pragma unroll
            for (int mt = 0; mt < 2; mt++) {
                const int r0 = warpRow + mt * 16 + g;
                af[mt][0] = As2[r0][kc0 + tg];
                af[mt][1] = As2[r0 + 8][kc0 + tg];
                af[mt][2] = As2[r0][kc0 + 4 + tg];
                af[mt][3] = As2[r0 + 8][kc0 + 4 + tg];
            }
            unsigned bf[8][2];
#pragma unroll
            for (int nt = 0; nt < 8; nt++) {
                const int c0 = warpCol + nt * 8 + g;
                bf[nt][0] = Bs2[kc0 + tg][c0];
                bf[nt][1] = Bs2[kc0 + 4 + tg][c0];
            }
#pragma unroll
            for (int mt = 0; mt < 2; mt++)
#pragma unroll
                for (int nt = 0; nt < 8; nt++)
                    mma_f16(acc[mt][nt], af[mt], bf[nt]);
        }
        __syncthreads();
        if (kt < TILES - 1) {
            SSTORE();
            __syncthreads();
        }
    }

    // epilogue: bias + store (c0,c1 contiguous)
#pragma unroll
    for (int mt = 0; mt < 2; mt++) {
        const int row = rowBase + warpRow + mt * 16 + g;
#pragma unroll
        for (int nt = 0; nt < 8; nt++) {
            const int col = colBase + warpCol + nt * 8 + tg * 2;
            const float2 bv = *(const float2*)(bias + col);
            storeC2<TOUT>(C, (size_t)row * NDIM + col,
                          acc[mt][nt][0] + bv.x, acc[mt][nt][1] + bv.y);
            storeC2<TOUT>(C, (size_t)(row + 8) * NDIM + col,
                          acc[mt][nt][2] + bv.x, acc[mt][nt][3] + bv.y);
        }
    }
#undef GLOAD
#undef SSTORE
}

// ------------------------- deformable sampling + softmax + aggregate -----------------------
// 1 block per pixel, 8 warps = 8 heads, lane = channel d (0..31). sf tiles are fp16.
__global__ __launch_bounds__(256)
void sample_kernel(const float* __restrict__ refp)
{
    const int pixel = blockIdx.x;
    const int b = pixel / (H_ * W_);
    const int rem = pixel - b * (H_ * W_);
    const int h = threadIdx.x >> 5;
    const int d = threadIdx.x & 31;

    // torch .repeat quirk: ref for bh-index n = b*NH+h is ref_point[n % B]
    const int rb = (b * NH_ + h) % B_;
    const int refIdx = (rb * (H_ * W_) + rem) * 2;
    const float ry = refp[refIdx + 0];
    const float rx = refp[refIdx + 1];

    const float* Arow = g_offA + (size_t)pixel * NOAP + 128 + h * 8;
    float lg[8];
    float mx = -1e30f;
#pragma unroll
    for (int j = 0; j < 8; j++) { lg[j] = Arow[j]; mx = fmaxf(mx, lg[j]); }
    float ssum = 0.f;
#pragma unroll
    for (int j = 0; j < 8; j++) { lg[j] = expf(lg[j] - mx); ssum += lg[j]; }
    const float inv = 1.f / ssum;

    const float* offrow = g_offA + (size_t)pixel * NOAP + h * 16;

    const float sy = (float)H_ / (float)(H_ - 1);
    const float sx = (float)W_ / (float)(W_ - 1);

    float acc = 0.f;
#pragma unroll
    for (int l = 0; l < 2; l++) {
        const __half* sf = l ? g_sf1h : g_sf0h;
        const __half* sfb = sf + (size_t)b * (H_ * W_) * DM_ + h * 32 + d;
#pragma unroll
        for (int k = 0; k < 4; k++) {
            const float py = (ry + offrow[l * 8 + k * 2 + 0]) * sy - 0.5f;
            const float px = (rx + offrow[l * 8 + k * 2 + 1]) * sx - 0.5f;
            const float w  = lg[l * 4 + k] * inv;

            const float fy = floorf(py), fx = floorf(px);
            const int y0 = (int)fy, x0 = (int)fx;
            const float wy1 = py - fy, wx1 = px - fx;
            const float wy0 = 1.f - wy1, wx0 = 1.f - wx1;

            const bool yv0 = (y0 >= 0) && (y0 < H_);
            const bool yv1 = (y0 + 1 >= 0) && (y0 + 1 < H_);
            const bool xv0 = (x0 >= 0) && (x0 < W_);
            const bool xv1 = (x0 + 1 >= 0) && (x0 + 1 < W_);

            float v00 = 0.f, v01 = 0.f, v10 = 0.f, v11 = 0.f;
            if (yv0 && xv0) v00 = __half2float(sfb[(size_t)(y0 * W_ + x0) * DM_]);
            if (yv0 && xv1) v01 = __half2float(sfb[(size_t)(y0 * W_ + x0 + 1) * DM_]);
            if (yv1 && xv0) v10 = __half2float(sfb[(size_t)((y0 + 1) * W_ + x0) * DM_]);
            if (yv1 && xv1) v11 = __half2float(sfb[(size_t)((y0 + 1) * W_ + x0 + 1) * DM_]);

            acc += w * (wy0 * (wx0 * v00 + wx1 * v01) + wy1 * (wx0 * v10 + wx1 * v11));
        }
    }
    g_feath[(size_t)pixel * DM_ + h * 32 + d] = __float2half_rn(acc);
}

// ------------------------- launch -------------------------
extern "C" void kernel_launch(void* const* d_in, const int* in_sizes, int n_in,
                              void* d_out, int out_size)
{
    const float* query = (const float*)d_in[0];
    const float* keys0 = (const float*)d_in[1];
    const float* keys1 = (const float*)d_in[2];
    const float* refp  = (const float*)d_in[3];
    const float* Wq = (const float*)d_in[4];
    const float* bq = (const float*)d_in[5];
    const float* Wk = (const float*)d_in[6];
    const float* bk = (const float*)d_in[7];
    const float* Wo = (const float*)d_in[8];
    const float* bo = (const float*)d_in[9];
    const float* Wa = (const float*)d_in[10];
    const float* ba = (const float*)d_in[11];
    const float* Wm = (const float*)d_in[12];
    const float* bm = (const float*)d_in[13];
    float* out = (float*)d_out;

    __half *sf0h, *sf1h, *feath;
    float *offA, *Weff, *beff;
    cudaGetSymbolAddress((void**)&sf0h,  g_sf0h);
    cudaGetSymbolAddress((void**)&sf1h,  g_sf1h);
    cudaGetSymbolAddress((void**)&feath, g_feath);
    cudaGetSymbolAddress((void**)&offA,  g_offA);
    cudaGetSymbolAddress((void**)&Weff,  g_Weff);
    cudaGetSymbolAddress((void**)&beff,  g_beff);

    weff_kernel<<<DM_, 256>>>(Wq, Wo, Wa);
    beff_kernel<<<1, 256>>>(bq, Wo, Wa, bo, ba);

    dim3 gg(NDIM / 128, NPIX / 128);   // (2, 256)
    gemm_f16<float, float ><<<gg, 256>>>(query, Weff, beff, offA);
    gemm_f16<float, __half><<<gg, 256>>>(keys0, Wk, bk, sf0h);
    gemm_f16<float, __half><<<gg, 256>>>(keys1, Wk, bk, sf1h);

    sample_kernel<<<NPIX, 256>>>(refp);

    gemm_f16<__half, float><<<gg, 256>>>(feath, Wm, bm, out);

    (void)in_sizes; (void)n_in; (void)out_size;
}

// round 8
// speedup vs baseline: 2.9560x; 1.3896x over previous
#include <cuda_runtime.h>
#include <cuda_fp16.h>
#include <cstdint>
#include <math.h>

#define B_   4
#define H_   64
#define W_   128
#define DM_  256
#define NH_  8
#define NPIX (B_*H_*W_)      // 32768
#define NOAP 256             // padded offA width (128 off + 64 attn + 64 pad)
#define KDIM 256
#define NDIM 256

// ------------------------- scratch (device globals; no allocation) -------------------------
__device__ __align__(256) __half g_sf0h [NPIX*DM_];
__device__ __align__(256) __half g_sf1h [NPIX*DM_];
__device__ __align__(256) __half g_feath[NPIX*DM_];
__device__ __align__(256) float  g_offA [NPIX*NOAP];
__device__ __align__(256) float  g_Weff [DM_*NOAP];
__device__ __align__(256) float  g_beff [NOAP];

// ------------------------- Weff = Wq @ [Wo | Wa | 0],  beff = bq @ Wcat + [bo|ba|0] --------
__global__ void weff_kernel(const float* __restrict__ Wq, const float* __restrict__ Wo,
                            const float* __restrict__ Wa)
{
    __shared__ float wq[DM_];
    const int r = blockIdx.x;
    const int c = threadIdx.x;
    wq[c] = Wq[r * DM_ + c];
    __syncthreads();
    float acc = 0.f;
    if (c < 128) {
        for (int k = 0; k < DM_; k++) acc += wq[k] * Wo[k * 128 + c];
    } else if (c < 192) {
        const int cc = c - 128;
        for (int k = 0; k < DM_; k++) acc += wq[k] * Wa[k * 64 + cc];
    }
    g_Weff[r * NOAP + c] = (c < 192) ? acc : 0.f;
}

__global__ void beff_kernel(const float* __restrict__ bq, const float* __restrict__ Wo,
                            const float* __restrict__ Wa, const float* __restrict__ bo,
                            const float* __restrict__ ba)
{
    const int c = threadIdx.x;
    float acc = 0.f;
    if (c < 128) {
        for (int k = 0; k < DM_; k++) acc += bq[k] * Wo[k * 128 + c];
        acc += bo[c];
    } else if (c < 192) {
        const int cc = c - 128;
        for (int k = 0; k < DM_; k++) acc += bq[k] * Wa[k * 64 + cc];
        acc += ba[cc];
    }
    g_beff[c] = (c < 192) ? acc : 0.f;
}

// ------------------------- FP16 tensor-core GEMM core --------------------------------------
// CTA tile 128x128x32, 8 warps (4m x 2n), warp tile 32x64 = 2x8 m16n8k16 mma tiles.
// Double-buffered smem (one sync per K-tile); fp32->fp16 rn at staging; conflict-free LDS.

__device__ __forceinline__ unsigned pack2(float x, float y) {
    __half2 h = __floats2half2_rn(x, y);
    return *reinterpret_cast<unsigned*>(&h);
}

template<typename T>
__device__ __forceinline__ uint2 loadA4(const T* p);
template<>
__device__ __forceinline__ uint2 loadA4<float>(const float* p) {
    float4 v = *(const float4*)p;
    return make_uint2(pack2(v.x, v.y), pack2(v.z, v.w));
}
template<>
__device__ __forceinline__ uint2 loadA4<__half>(const __half* p) {
    return *(const uint2*)p;
}

template<typename T>
__device__ __forceinline__ void storeC2(T* C, size_t idx, float v0, float v1);
template<>
__device__ __forceinline__ void storeC2<float>(float* C, size_t idx, float v0, float v1) {
    *(float2*)(C + idx) = make_float2(v0, v1);
}
template<>
__device__ __forceinline__ void storeC2<__half>(__half* C, size_t idx, float v0, float v1) {
    *(unsigned*)(C + idx) = pack2(v0, v1);
}

__device__ __forceinline__ void mma_f16(float c[4], const unsigned a[4], const unsigned b[2]) {
    asm volatile(
        "mma.sync.aligned.m16n8k16.row.col.f32.f16.f16.f32 "
        "{%0,%1,%2,%3}, {%4,%5,%6,%7}, {%8,%9}, {%0,%1,%2,%3};"
        : "+f"(c[0]), "+f"(c[1]), "+f"(c[2]), "+f"(c[3])
        : "r"(a[0]), "r"(a[1]), "r"(a[2]), "r"(a[3]), "r"(b[0]), "r"(b[1]));
}

template<typename TIN, typename TOUT>
__device__ __forceinline__
void gemm_core(const TIN* __restrict__ A, const float* __restrict__ Bm,
               const float* __restrict__ bias, TOUT* __restrict__ C)
{
    // As2[buf][m][c]: half2 = A[m][2c..2c+1]; stride 20 -> frag banks (20g+tg)%32 bijective
    __shared__ unsigned As2[2][128][20];
    // Bs2[buf][p][n]: half2 = B[2p..2p+1][n]; stride 136 -> frag banks (8tg+g)%32 bijective
    __shared__ unsigned Bs2[2][16][136];

    const int tid  = threadIdx.x;
    const int lane = tid & 31;
    const int wid  = tid >> 5;
    const int g    = lane >> 2;
    const int tg   = lane & 3;
    const int warpRow = (wid & 3) * 32;
    const int warpCol = (wid >> 2) * 64;
    const int rowBase = blockIdx.y * 128;
    const int colBase = blockIdx.x * 128;

    const int am  = tid >> 3;          // A row 0..31 (+32*i)
    const int akc = (tid & 7) * 4;     // A k element offset
    const int ac2 = (tid & 7) * 2;     // A half2 slot
    const int bp  = tid >> 5;          // B k-pair 0..7 (+8)
    const int bnc = (tid & 31) * 4;    // B n col chunk

    const TIN*   Ap = A + (size_t)rowBase * KDIM;
    const float* Bp = Bm + colBase;

    uint2  ra[4];
    float4 rbf[4];

#define GLOAD(kt)                                                                       \
    {                                                                                   \
        _Pragma("unroll")                                                               \
        for (int i = 0; i < 4; i++)                                                     \
            ra[i] = loadA4<TIN>(Ap + (size_t)(am + 32 * i) * KDIM + (kt) * 32 + akc);   \
        rbf[0] = *(const float4*)(Bp + (size_t)((kt) * 32 + 2 * bp     ) * NDIM + bnc); \
        rbf[1] = *(const float4*)(Bp + (size_t)((kt) * 32 + 2 * bp +  1) * NDIM + bnc); \
        rbf[2] = *(const float4*)(Bp + (size_t)((kt) * 32 + 2 * bp + 16) * NDIM + bnc); \
        rbf[3] = *(const float4*)(Bp + (size_t)((kt) * 32 + 2 * bp + 17) * NDIM + bnc); \
    }

#define SSTORE(buf)                                                                     \
    {                                                                                   \
        _Pragma("unroll")                                                               \
        for (int i = 0; i < 4; i++)                                                     \
            *(uint2*)(&As2[buf][am + 32 * i][ac2]) = ra[i];                             \
        *(uint4*)(&Bs2[buf][bp][bnc]) = make_uint4(                                     \
            pack2(rbf[0].x, rbf[1].x), pack2(rbf[0].y, rbf[1].y),                       \
            pack2(rbf[0].z, rbf[1].z), pack2(rbf[0].w, rbf[1].w));                      \
        *(uint4*)(&Bs2[buf][bp + 8][bnc]) = make_uint4(                                 \
            pack2(rbf[2].x, rbf[3].x), pack2(rbf[2].y, rbf[3].y),                       \
            pack2(rbf[2].z, rbf[3].z), pack2(rbf[2].w, rbf[3].w));                      \
    }

    float acc[2][8][4];
#pragma unroll
    for (int mt = 0; mt < 2; mt++)
#pragma unroll
        for (int nt = 0; nt < 8; nt++)
#pragma unroll
            for (int j = 0; j < 4; j++) acc[mt][nt][j] = 0.f;

    GLOAD(0);
    SSTORE(0);
    __syncthreads();

    const int TILES = KDIM / 32;   // 8
#pragma unroll
    for (int kt = 0; kt < TILES; kt++) {
        const int cur = kt & 1;
        if (kt < TILES - 1) GLOAD(kt + 1);

#pragma unroll
        for (int s = 0; s < 2; s++) {
            const int kc0 = s * 8;
            unsigned af[2][4];
#pragma unroll
            for (int mt = 0; mt < 2; mt++) {
                const int r0 = warpRow + mt * 16 + g;
                af[mt][0] = As2[cur][r0][kc0 + tg];
                af[mt][1] = As2[cur][r0 + 8][kc0 + tg];
                af[mt][2] = As2[cur][r0][kc0 + 4 + tg];
                af[mt][3] = As2[cur][r0 + 8][kc0 + 4 + tg];
            }
            unsigned bf[8][2];
#pragma unroll
            for (int nt = 0; nt < 8; nt++) {
                const int c0 = warpCol + nt * 8 + g;
                bf[nt][0] = Bs2[cur][kc0 + tg][c0];
                bf[nt][1] = Bs2[cur][kc0 + 4 + tg][c0];
            }
#pragma unroll
            for (int mt = 0; mt < 2; mt++)
#pragma unroll
                for (int nt = 0; nt < 8; nt++)
                    mma_f16(acc[mt][nt], af[mt], bf[nt]);
        }
        if (kt < TILES - 1) SSTORE(1 - cur);
        __syncthreads();
    }

#pragma unroll
    for (int mt = 0; mt < 2; mt++) {
        const int row = rowBase + warpRow + mt * 16 + g;
#pragma unroll
        for (int nt = 0; nt < 8; nt++) {
            const int col = colBase + warpCol + nt * 8 + tg * 2;
            const float2 bv = *(const float2*)(bias + col);
            storeC2<TOUT>(C, (size_t)row * NDIM + col,
                          acc[mt][nt][0] + bv.x, acc[mt][nt][1] + bv.y);
            storeC2<TOUT>(C, (size_t)(row + 8) * NDIM + col,
                          acc[mt][nt][2] + bv.x, acc[mt][nt][3] + bv.y);
        }
    }
#undef GLOAD
#undef SSTORE
}

template<typename TIN, typename TOUT>
__global__ __launch_bounds__(256)
void gemm_f16(const TIN* __restrict__ A, const float* __restrict__ Bm,
              const float* __restrict__ bias, TOUT* __restrict__ C)
{
    gemm_core<TIN, TOUT>(A, Bm, bias, C);
}

// keys0/keys1 share B=Wk, bias=bk; blockIdx.z picks input/output.
__global__ __launch_bounds__(256)
void gemm_keys(const float* __restrict__ A0, const float* __restrict__ A1,
               const float* __restrict__ Bm, const float* __restrict__ bias,
               __half* __restrict__ C0, __half* __restrict__ C1)
{
    if (blockIdx.z == 0) gemm_core<float, __half>(A0, Bm, bias, C0);
    else                 gemm_core<float, __half>(A1, Bm, bias, C1);
}

// ------------------------- deformable sampling: two-phase ----------------------------------
// Block = 2 pixels. Phase 1 (128 thr): per (pixel,head,point) softmax weight + 4 clamped
// corner indices + 4 premultiplied corner weights (0 if OOB). Phase 2 (256 thr):
// 2 px x 8 heads x 16 lanes, each lane gathers half2 (2 channels), branch-free.
__global__ __launch_bounds__(256)
void sample_kernel(const float* __restrict__ refp)
{
    __shared__ float s_w [2][NH_][8][4];
    __shared__ int   s_ix[2][NH_][8][4];

    const int blk = blockIdx.x;
    const int tid = threadIdx.x;

    if (tid < 128) {
        const int j   = tid & 7;          // point
        const int grp = tid >> 3;         // 0..15
        const int sub = grp >> 3;         // pixel within block
        const int h   = grp & 7;          // head
        const int pixel = blk * 2 + sub;
        const int b = pixel / (H_ * W_);
        const int rem = pixel - b * (H_ * W_);
        // torch .repeat quirk: ref for bh-index n = b*NH+h is ref_point[n % B]
        const int rb = (b * NH_ + h) % B_;
        const float ry = refp[(rb * (H_ * W_) + rem) * 2 + 0];
        const float rx = refp[(rb * (H_ * W_) + rem) * 2 + 1];

        const float lgj = g_offA[(size_t)pixel * NOAP + 128 + h * 8 + j];
        float mx = lgj;
#pragma unroll
        for (int o = 4; o; o >>= 1) mx = fmaxf(mx, __shfl_xor_sync(0xffffffffu, mx, o, 8));
        const float e = expf(lgj - mx);
        float s = e;
#pragma unroll
        for (int o = 4; o; o >>= 1) s += __shfl_xor_sync(0xffffffffu, s, o, 8);
        const float w = e / s;

        const float offy = g_offA[(size_t)pixel * NOAP + h * 16 + j * 2 + 0];
        const float offx = g_offA[(size_t)pixel * NOAP + h * 16 + j * 2 + 1];
        const float py = (ry + offy) * ((float)H_ / (float)(H_ - 1)) - 0.5f;
        const float px = (rx + offx) * ((float)W_ / (float)(W_ - 1)) - 0.5f;
        const float fy = floorf(py), fx = floorf(px);
        const int y0 = (int)fy, x0 = (int)fx;
        const float wy1 = py - fy, wx1 = px - fx;
        const float wy0 = 1.f - wy1, wx0 = 1.f - wx1;
        const bool yv0 = (y0 >= 0) && (y0 < H_);
        const bool yv1 = (y0 + 1 >= 0) && (y0 + 1 < H_);
        const bool xv0 = (x0 >= 0) && (x0 < W_);
        const bool xv1 = (x0 + 1 >= 0) && (x0 + 1 < W_);
        const int y0c = min(max(y0, 0), H_ - 1), y1c = min(max(y0 + 1, 0), H_ - 1);
        const int x0c = min(max(x0, 0), W_ - 1), x1c = min(max(x0 + 1, 0), W_ - 1);
        const int basepix = b * (H_ * W_);
        s_ix[sub][h][j][0] = (basepix + y0c * W_ + x0c) * DM_;
        s_ix[sub][h][j][1] = (basepix + y0c * W_ + x1c) * DM_;
        s_ix[sub][h][j][2] = (basepix + y1c * W_ + x0c) * DM_;
        s_ix[sub][h][j][3] = (basepix + y1c * W_ + x1c) * DM_;
        s_w [sub][h][j][0] = (yv0 && xv0) ? w * wy0 * wx0 : 0.f;
        s_w [sub][h][j][1] = (yv0 && xv1) ? w * wy0 * wx1 : 0.f;
        s_w [sub][h][j][2] = (yv1 && xv0) ? w * wy1 * wx0 : 0.f;
        s_w [sub][h][j][3] = (yv1 && xv1) ? w * wy1 * wx1 : 0.f;
    }
    __syncthreads();

    const int sub = tid >> 7;
    const int h = (tid >> 4) & 7;
    const int e = tid & 15;
    const int pixel = blk * 2 + sub;
    const int chan = h * 32 + e * 2;

    float ax = 0.f, ay = 0.f;
#pragma unroll
    for (int l = 0; l < 2; l++) {
        const __half* sf = l ? g_sf1h : g_sf0h;
#pragma unroll
        for (int k = 0; k < 4; k++) {
            const int j = l * 4 + k;
            const float4 w4 = *(const float4*)(s_w[sub][h][j]);
            const int4   i4 = *(const int4*)(s_ix[sub][h][j]);
            const float2 v0 = __half22float2(*(const __half2*)(sf + i4.x + chan));
            const float2 v1 = __half22float2(*(const __half2*)(sf + i4.y + chan));
            const float2 v2 = __half22float2(*(const __half2*)(sf + i4.z + chan));
            const float2 v3 = __half22float2(*(const __half2*)(sf + i4.w + chan));
            ax += w4.x * v0.x + w4.y * v1.x + w4.z * v2.x + w4.w * v3.x;
            ay += w4.x * v0.y + w4.y * v1.y + w4.z * v2.y + w4.w * v3.y;
        }
    }
    *(unsigned*)(g_feath + (size_t)pixel * DM_ + chan) = pack2(ax, ay);
}

// ------------------------- launch -------------------------
extern "C" void kernel_launch(void* const* d_in, const int* in_sizes, int n_in,
                              void* d_out, int out_size)
{
    const float* query = (const float*)d_in[0];
    const float* keys0 = (const float*)d_in[1];
    const float* keys1 = (const float*)d_in[2];
    const float* refp  = (const float*)d_in[3];
    const float* Wq = (const float*)d_in[4];
    const float* bq = (const float*)d_in[5];
    const float* Wk = (const float*)d_in[6];
    const float* bk = (const float*)d_in[7];
    const float* Wo = (const float*)d_in[8];
    const float* bo = (const float*)d_in[9];
    const float* Wa = (const float*)d_in[10];
    const float* ba = (const float*)d_in[11];
    const float* Wm = (const float*)d_in[12];
    const float* bm = (const float*)d_in[13];
    float* out = (float*)d_out;

    __half *sf0h, *sf1h, *feath;
    float *offA, *Weff, *beff;
    cudaGetSymbolAddress((void**)&sf0h,  g_sf0h);
    cudaGetSymbolAddress((void**)&sf1h,  g_sf1h);
    cudaGetSymbolAddress((void**)&feath, g_feath);
    cudaGetSymbolAddress((void**)&offA,  g_offA);
    cudaGetSymbolAddress((void**)&Weff,  g_Weff);
    cudaGetSymbolAddress((void**)&beff,  g_beff);

    weff_kernel<<<DM_, 256>>>(Wq, Wo, Wa);
    beff_kernel<<<1, 256>>>(bq, Wo, Wa, bo, ba);

    dim3 gg(NDIM / 128, NPIX / 128);       // (2, 256)
    gemm_f16<float, float><<<gg, 256>>>(query, Weff, beff, offA);

    dim3 gk(NDIM / 128, NPIX / 128, 2);    // (2, 256, 2)
    gemm_keys<<<gk, 256>>>(keys0, keys1, Wk, bk, sf0h, sf1h);

    sample_kernel<<<NPIX / 2, 256>>>(refp);

    gemm_f16<__half, float><<<gg, 256>>>(feath, Wm, bm, out);

    (void)in_sizes; (void)n_in; (void)out_size;
}

// round 10
// speedup vs baseline: 3.6588x; 1.2378x over previous
#include <cuda_runtime.h>
#include <cuda_fp16.h>
#include <cstdint>
#include <math.h>

#define B_   4
#define H_   64
#define W_   128
#define DM_  256
#define NH_  8
#define NPIX (B_*H_*W_)      // 32768
#define NOAP 256             // padded offA width (128 off + 64 attn + 64 pad)
#define KDIM 256
#define NDIM 256

#define AS_STRIDE 20
#define BS_STRIDE 136
#define AS_BUF (128*AS_STRIDE)   // 2560 words per buffer
#define BS_BUF (16*BS_STRIDE)    // 2176 words per buffer

// ------------------------- scratch (device globals; no allocation) -------------------------
__device__ __align__(256) __half g_sf0h [NPIX*DM_];
__device__ __align__(256) __half g_sf1h [NPIX*DM_];
__device__ __align__(256) __half g_feath[NPIX*DM_];
__device__ __align__(256) float  g_offA [NPIX*NOAP];
__device__ __align__(256) float  g_Weff [DM_*NOAP];
__device__ __align__(256) float  g_beff [NOAP];

// ------------------------- Weff = Wq @ [Wo | Wa | 0],  beff = bq @ Wcat + [bo|ba|0] --------
__global__ void weff_kernel(const float* __restrict__ Wq, const float* __restrict__ Wo,
                            const float* __restrict__ Wa)
{
    __shared__ float wq[DM_];
    const int r = blockIdx.x;
    const int c = threadIdx.x;
    wq[c] = Wq[r * DM_ + c];
    __syncthreads();
    float acc = 0.f;
    if (c < 128) {
        for (int k = 0; k < DM_; k++) acc += wq[k] * Wo[k * 128 + c];
    } else if (c < 192) {
        const int cc = c - 128;
        for (int k = 0; k < DM_; k++) acc += wq[k] * Wa[k * 64 + cc];
    }
    g_Weff[r * NOAP + c] = (c < 192) ? acc : 0.f;
}

__global__ void beff_kernel(const float* __restrict__ bq, const float* __restrict__ Wo,
                            const float* __restrict__ Wa, const float* __restrict__ bo,
                            const float* __restrict__ ba)
{
    const int c = threadIdx.x;
    float acc = 0.f;
    if (c < 128) {
        for (int k = 0; k < DM_; k++) acc += bq[k] * Wo[k * 128 + c];
        acc += bo[c];
    } else if (c < 192) {
        const int cc = c - 128;
        for (int k = 0; k < DM_; k++) acc += bq[k] * Wa[k * 64 + cc];
        acc += ba[cc];
    }
    g_beff[c] = (c < 192) ? acc : 0.f;
}

// ------------------------- FP16 tensor-core GEMM core --------------------------------------
// CTA tile 128x128x32, 8 warps (4m x 2n), warp tile 32x64 = 2x8 m16n8k16 mma tiles.
// Double-buffered smem (passed in from wrapper so template instantiations share it),
// one sync/K-tile; B packed to half2 at load; conflict-free fragment LDS; 2 CTAs/SM.

__device__ __forceinline__ unsigned pack2(float x, float y) {
    __half2 h = __floats2half2_rn(x, y);
    return *reinterpret_cast<unsigned*>(&h);
}

template<typename T>
__device__ __forceinline__ uint2 loadA4(const T* p);
template<>
__device__ __forceinline__ uint2 loadA4<float>(const float* p) {
    float4 v = *(const float4*)p;
    return make_uint2(pack2(v.x, v.y), pack2(v.z, v.w));
}
template<>
__device__ __forceinline__ uint2 loadA4<__half>(const __half* p) {
    return *(const uint2*)p;
}

template<typename T>
__device__ __forceinline__ void storeC2(T* C, size_t idx, float v0, float v1);
template<>
__device__ __forceinline__ void storeC2<float>(float* C, size_t idx, float v0, float v1) {
    *(float2*)(C + idx) = make_float2(v0, v1);
}
template<>
__device__ __forceinline__ void storeC2<__half>(__half* C, size_t idx, float v0, float v1) {
    *(unsigned*)(C + idx) = pack2(v0, v1);
}

__device__ __forceinline__ void mma_f16(float c[4], const unsigned a[4], const unsigned b[2]) {
    asm volatile(
        "mma.sync.aligned.m16n8k16.row.col.f32.f16.f16.f32 "
        "{%0,%1,%2,%3}, {%4,%5,%6,%7}, {%8,%9}, {%0,%1,%2,%3};"
        : "+f"(c[0]), "+f"(c[1]), "+f"(c[2]), "+f"(c[3])
        : "r"(a[0]), "r"(a[1]), "r"(a[2]), "r"(a[3]), "r"(b[0]), "r"(b[1]));
}

template<typename TIN, typename TOUT>
__device__ __forceinline__
void gemm_core(const TIN* __restrict__ A, const float* __restrict__ Bm,
               const float* __restrict__ bias, TOUT* __restrict__ C,
               unsigned* __restrict__ sAs, unsigned* __restrict__ sBs)
{
    // sAs[buf*AS_BUF + m*20 + c]: half2 = A[m][2c..2c+1]; banks (20g+tg)%32 bijective
    // sBs[buf*BS_BUF + p*136 + n]: half2 = B[2p..2p+1][n]; banks (8tg+g)%32 bijective
    const int tid  = threadIdx.x;
    const int lane = tid & 31;
    const int wid  = tid >> 5;
    const int g    = lane >> 2;
    const int tg   = lane & 3;
    const int warpRow = (wid & 3) * 32;
    const int warpCol = (wid >> 2) * 64;
    const int rowBase = blockIdx.y * 128;
    const int colBase = blockIdx.x * 128;

    const int am  = tid >> 3;          // A row 0..31 (+32*i)
    const int akc = (tid & 7) * 4;     // A k element offset
    const int ac2 = (tid & 7) * 2;     // A half2 slot
    const int bp  = tid >> 5;          // B k-pair 0..7 (+8)
    const int bnc = (tid & 31) * 4;    // B n col chunk

    const TIN*   Ap = A + (size_t)rowBase * KDIM;
    const float* Bp = Bm + colBase;

    uint2    ra[4];
    unsigned rbp[8];

#define GLOAD(kt)                                                                         \
    {                                                                                     \
        _Pragma("unroll")                                                                 \
        for (int i = 0; i < 4; i++)                                                       \
            ra[i] = loadA4<TIN>(Ap + (size_t)(am + 32 * i) * KDIM + (kt) * 32 + akc);     \
        {                                                                                 \
            float4 b0 = *(const float4*)(Bp + (size_t)((kt) * 32 + 2 * bp    ) * NDIM + bnc); \
            float4 b1 = *(const float4*)(Bp + (size_t)((kt) * 32 + 2 * bp + 1) * NDIM + bnc); \
            rbp[0] = pack2(b0.x, b1.x); rbp[1] = pack2(b0.y, b1.y);                       \
            rbp[2] = pack2(b0.z, b1.z); rbp[3] = pack2(b0.w, b1.w);                       \
            float4 b2 = *(const float4*)(Bp + (size_t)((kt) * 32 + 2 * bp + 16) * NDIM + bnc); \
            float4 b3 = *(const float4*)(Bp + (size_t)((kt) * 32 + 2 * bp + 17) * NDIM + bnc); \
            rbp[4] = pack2(b2.x, b3.x); rbp[5] = pack2(b2.y, b3.y);                       \
            rbp[6] = pack2(b2.z, b3.z); rbp[7] = pack2(b2.w, b3.w);                       \
        }                                                                                 \
    }

#define SSTORE(buf)                                                                       \
    {                                                                                     \
        _Pragma("unroll")                                                                 \
        for (int i = 0; i < 4; i++)                                                       \
            *(uint2*)(&sAs[(buf)*AS_BUF + (am + 32 * i)*AS_STRIDE + ac2]) = ra[i];        \
        *(uint4*)(&sBs[(buf)*BS_BUF + bp*BS_STRIDE + bnc])                                \
            = make_uint4(rbp[0], rbp[1], rbp[2], rbp[3]);                                 \
        *(uint4*)(&sBs[(buf)*BS_BUF + (bp + 8)*BS_STRIDE + bnc])                          \
            = make_uint4(rbp[4], rbp[5], rbp[6], rbp[7]);                                 \
    }

    float acc[2][8][4];
#pragma unroll
    for (int mt = 0; mt < 2; mt++)
#pragma unroll
        for (int nt = 0; nt < 8; nt++)
#pragma unroll
            for (int j = 0; j < 4; j++) acc[mt][nt][j] = 0.f;

    GLOAD(0);
    SSTORE(0);
    __syncthreads();

    const int TILES = KDIM / 32;   // 8
#pragma unroll
    for (int kt = 0; kt < TILES; kt++) {
        const int cur = kt & 1;
        if (kt < TILES - 1) GLOAD(kt + 1);

        const unsigned* As = sAs + cur * AS_BUF;
        const unsigned* Bs = sBs + cur * BS_BUF;
#pragma unroll
        for (int s = 0; s < 2; s++) {
            const int kc0 = s * 8;
            unsigned af[2][4];
#pragma unroll
            for (int mt = 0; mt < 2; mt++) {
                const int r0 = warpRow + mt * 16 + g;
                af[mt][0] = As[r0 * AS_STRIDE + kc0 + tg];
                af[mt][1] = As[(r0 + 8) * AS_STRIDE + kc0 + tg];
                af[mt][2] = As[r0 * AS_STRIDE + kc0 + 4 + tg];
                af[mt][3] = As[(r0 + 8) * AS_STRIDE + kc0 + 4 + tg];
            }
            unsigned bf[8][2];
#pragma unroll
            for (int nt = 0; nt < 8; nt++) {
                const int c0 = warpCol + nt * 8 + g;
                bf[nt][0] = Bs[(kc0 + tg) * BS_STRIDE + c0];
                bf[nt][1] = Bs[(kc0 + 4 + tg) * BS_STRIDE + c0];
            }
#pragma unroll
            for (int mt = 0; mt < 2; mt++)
#pragma unroll
                for (int nt = 0; nt < 8; nt++)
                    mma_f16(acc[mt][nt], af[mt], bf[nt]);
        }
        if (kt < TILES - 1) SSTORE(1 - cur);
        __syncthreads();
    }

#pragma unroll
    for (int mt = 0; mt < 2; mt++) {
        const int row = rowBase + warpRow + mt * 16 + g;
#pragma unroll
        for (int nt = 0; nt < 8; nt++) {
            const int col = colBase + warpCol + nt * 8 + tg * 2;
            const float2 bv = *(const float2*)(bias + col);
            storeC2<TOUT>(C, (size_t)row * NDIM + col,
                          acc[mt][nt][0] + bv.x, acc[mt][nt][1] + bv.y);
            storeC2<TOUT>(C, (size_t)(row + 8) * NDIM + col,
                          acc[mt][nt][2] + bv.x, acc[mt][nt][3] + bv.y);
        }
    }
#undef GLOAD
#undef SSTORE
}

// All 3 head GEMMs in one launch (grid.z picks which); shared smem buffer across
// template instantiations (hoisted here to stay under the 48KB static limit).
__global__ __launch_bounds__(256, 2)
void gemm_heads(const float* __restrict__ query, const float* __restrict__ Weff,
                const float* __restrict__ beff,  float* __restrict__ offA,
                const float* __restrict__ keys0, const float* __restrict__ keys1,
                const float* __restrict__ Wk,    const float* __restrict__ bk,
                __half* __restrict__ sf0h, __half* __restrict__ sf1h)
{
    __shared__ __align__(16) unsigned sAs[2 * AS_BUF];
    __shared__ __align__(16) unsigned sBs[2 * BS_BUF];
    if (blockIdx.z == 0)      gemm_core<float, float >(query, Weff, beff, offA, sAs, sBs);
    else if (blockIdx.z == 1) gemm_core<float, __half>(keys0, Wk, bk, sf0h, sAs, sBs);
    else                      gemm_core<float, __half>(keys1, Wk, bk, sf1h, sAs, sBs);
}

__global__ __launch_bounds__(256, 2)
void gemm_out(const __half* __restrict__ A, const float* __restrict__ Bm,
              const float* __restrict__ bias, float* __restrict__ C)
{
    __shared__ __align__(16) unsigned sAs[2 * AS_BUF];
    __shared__ __align__(16) unsigned sBs[2 * BS_BUF];
    gemm_core<__half, float>(A, Bm, bias, C, sAs, sBs);
}

// ------------------------- deformable sampling: two-phase ----------------------------------
// Block = 2 pixels. Phase 1 (128 thr): per (pixel,head,point) softmax weight + 4 clamped
// corner indices + 4 premultiplied corner weights (0 if OOB). Phase 2 (256 thr):
// 2 px x 8 heads x 16 lanes, each lane gathers half2 (2 channels), branch-free.
__global__ __launch_bounds__(256)
void sample_kernel(const float* __restrict__ refp)
{
    __shared__ float s_w [2][NH_][8][4];
    __shared__ int   s_ix[2][NH_][8][4];

    const int blk = blockIdx.x;
    const int tid = threadIdx.x;

    if (tid < 128) {
        const int j   = tid & 7;          // point
        const int grp = tid >> 3;         // 0..15
        const int sub = grp >> 3;         // pixel within block
        const int h   = grp & 7;          // head
        const int pixel = blk * 2 + sub;
        const int b = pixel / (H_ * W_);
        const int rem = pixel - b * (H_ * W_);
        // torch .repeat quirk: ref for bh-index n = b*NH+h is ref_point[n % B]
        const int rb = (b * NH_ + h) % B_;
        const float ry = refp[(rb * (H_ * W_) + rem) * 2 + 0];
        const float rx = refp[(rb * (H_ * W_) + rem) * 2 + 1];

        const float lgj = g_offA[(size_t)pixel * NOAP + 128 + h * 8 + j];
        float mx = lgj;
#pragma unroll
        for (int o = 4; o; o >>= 1) mx = fmaxf(mx, __shfl_xor_sync(0xffffffffu, mx, o, 8));
        const float e = expf(lgj - mx);
        float s = e;
#pragma unroll
        for (int o = 4; o; o >>= 1) s += __shfl_xor_sync(0xffffffffu, s, o, 8);
        const float w = e / s;

        const float offy = g_offA[(size_t)pixel * NOAP + h * 16 + j * 2 + 0];
        const float offx = g_offA[(size_t)pixel * NOAP + h * 16 + j * 2 + 1];
        const float py = (ry + offy) * ((float)H_ / (float)(H_ - 1)) - 0.5f;
        const float px = (rx + offx) * ((float)W_ / (float)(W_ - 1)) - 0.5f;
        const float fy = floorf(py), fx = floorf(px);
        const int y0 = (int)fy, x0 = (int)fx;
        const float wy1 = py - fy, wx1 = px - fx;
        const float wy0 = 1.f - wy1, wx0 = 1.f - wx1;
        const bool yv0 = (y0 >= 0) && (y0 < H_);
        const bool yv1 = (y0 + 1 >= 0) && (y0 + 1 < H_);
        const bool xv0 = (x0 >= 0) && (x0 < W_);
        const bool xv1 = (x0 + 1 >= 0) && (x0 + 1 < W_);
        const int y0c = min(max(y0, 0), H_ - 1), y1c = min(max(y0 + 1, 0), H_ - 1);
        const int x0c = min(max(x0, 0), W_ - 1), x1c = min(max(x0 + 1, 0), W_ - 1);
        const int basepix = b * (H_ * W_);
        s_ix[sub][h][j][0] = (basepix + y0c * W_ + x0c) * DM_;
        s_ix[sub][h][j][1] = (basepix + y0c * W_ + x1c) * DM_;
        s_ix[sub][h][j][2] = (basepix + y1c * W_ + x0c) * DM_;
        s_ix[sub][h][j][3] = (basepix + y1c * W_ + x1c) * DM_;
        s_w [sub][h][j][0] = (yv0 && xv0) ? w * wy0 * wx0 : 0.f;
        s_w [sub][h][j][1] = (yv0 && xv1) ? w * wy0 * wx1 : 0.f;
        s_w [sub][h][j][2] = (yv1 && xv0) ? w * wy1 * wx0 : 0.f;
        s_w [sub][h][j][3] = (yv1 && xv1) ? w * wy1 * wx1 : 0.f;
    }
    __syncthreads();

    const int sub = tid >> 7;
    const int h = (tid >> 4) & 7;
    const int e = tid & 15;
    const int pixel = blk * 2 + sub;
    const int chan = h * 32 + e * 2;

    float ax = 0.f, ay = 0.f;
#pragma unroll
    for (int l = 0; l < 2; l++) {
        const __half* sf = l ? g_sf1h : g_sf0h;
#pragma unroll
        for (int k = 0; k < 4; k++) {
            const int j = l * 4 + k;
            const float4 w4 = *(const float4*)(s_w[sub][h][j]);
            const int4   i4 = *(const int4*)(s_ix[sub][h][j]);
            const float2 v0 = __half22float2(*(const __half2*)(sf + i4.x + chan));
            const float2 v1 = __half22float2(*(const __half2*)(sf + i4.y + chan));
            const float2 v2 = __half22float2(*(const __half2*)(sf + i4.z + chan));
            const float2 v3 = __half22float2(*(const __half2*)(sf + i4.w + chan));
            ax += w4.x * v0.x + w4.y * v1.x + w4.z * v2.x + w4.w * v3.x;
            ay += w4.x * v0.y + w4.y * v1.y + w4.z * v2.y + w4.w * v3.y;
        }
    }
    *(unsigned*)(g_feath + (size_t)pixel * DM_ + chan) = pack2(ax, ay);
}

// ------------------------- launch -------------------------
extern "C" void kernel_launch(void* const* d_in, const int* in_sizes, int n_in,
                              void* d_out, int out_size)
{
    const float* query = (const float*)d_in[0];
    const float* keys0 = (const float*)d_in[1];
    const float* keys1 = (const float*)d_in[2];
    const float* refp  = (const float*)d_in[3];
    const float* Wq = (const float*)d_in[4];
    const float* bq = (const float*)d_in[5];
    const float* Wk = (const float*)d_in[6];
    const float* bk = (const float*)d_in[7];
    const float* Wo = (const float*)d_in[8];
    const float* bo = (const float*)d_in[9];
    const float* Wa = (const float*)d_in[10];
    const float* ba = (const float*)d_in[11];
    const float* Wm = (const float*)d_in[12];
    const float* bm = (const float*)d_in[13];
    float* out = (float*)d_out;

    __half *sf0h, *sf1h, *feath;
    float *offA, *Weff, *beff;
    cudaGetSymbolAddress((void**)&sf0h,  g_sf0h);
    cudaGetSymbolAddress((void**)&sf1h,  g_sf1h);
    cudaGetSymbolAddress((void**)&feath, g_feath);
    cudaGetSymbolAddress((void**)&offA,  g_offA);
    cudaGetSymbolAddress((void**)&Weff,  g_Weff);
    cudaGetSymbolAddress((void**)&beff,  g_beff);

    weff_kernel<<<DM_, 256>>>(Wq, Wo, Wa);
    beff_kernel<<<1, 256>>>(bq, Wo, Wa, bo, ba);

    dim3 gh(NDIM / 128, NPIX / 128, 3);    // (2, 256, 3)
    gemm_heads<<<gh, 256>>>(query, Weff, beff, offA, keys0, keys1, Wk, bk, sf0h, sf1h);

    sample_kernel<<<NPIX / 2, 256>>>(refp);

    dim3 gg(NDIM / 128, NPIX / 128);       // (2, 256)
    gemm_out<<<gg, 256>>>(feath, Wm, bm, out);

    (void)in_sizes; (void)n_in; (void)out_size;
}

// round 11
// speedup vs baseline: 4.2118x; 1.1511x over previous
#include <cuda_runtime.h>
#include <cuda_fp16.h>
#include <cstdint>
#include <math.h>

#define B_   4
#define H_   64
#define W_   128
#define DM_  256
#define NH_  8
#define NPIX (B_*H_*W_)      // 32768
#define NOAP 256             // padded offA width (128 off + 64 attn + 64 pad)
#define KDIM 256
#define NDIM 256

#define AS_STRIDE 20
#define BS_STRIDE 136
#define AS_BUF (128*AS_STRIDE)   // 2560 words per buffer
#define BS_BUF (16*BS_STRIDE)    // 2176 words per buffer

// ------------------------- scratch (device globals; no allocation) -------------------------
__device__ __align__(256) __half g_sf0h [NPIX*DM_];
__device__ __align__(256) __half g_sf1h [NPIX*DM_];
__device__ __align__(256) __half g_feath[NPIX*DM_];
__device__ __align__(256) float  g_offA [NPIX*NOAP];
__device__ __align__(256) float  g_Weff [DM_*NOAP];
__device__ __align__(256) float  g_beff [NOAP];

// --------- Weff = Wq @ [Wo | Wa | 0] (blocks 0..255), beff = bq@Wcat + [bo|ba|0] (block 256)
__global__ void wbeff_kernel(const float* __restrict__ Wq, const float* __restrict__ Wo,
                             const float* __restrict__ Wa, const float* __restrict__ bq,
                             const float* __restrict__ bo, const float* __restrict__ ba)
{
    __shared__ float wq[DM_];
    const int r = blockIdx.x;
    const int c = threadIdx.x;
    const bool isBias = (r == DM_);
    wq[c] = isBias ? bq[c] : Wq[r * DM_ + c];
    __syncthreads();
    float acc = 0.f;
    if (c < 128) {
        for (int k = 0; k < DM_; k++) acc += wq[k] * Wo[k * 128 + c];
        if (isBias) acc += bo[c];
    } else if (c < 192) {
        const int cc = c - 128;
        for (int k = 0; k < DM_; k++) acc += wq[k] * Wa[k * 64 + cc];
        if (isBias) acc += ba[cc];
    }
    if (isBias) g_beff[c] = (c < 192) ? acc : 0.f;
    else        g_Weff[r * NOAP + c] = (c < 192) ? acc : 0.f;
}

// ------------------------- FP16 tensor-core GEMM core --------------------------------------
// CTA tile 128x128x32, 8 warps (4m x 2n), warp tile 32x64 = 2x8 m16n8k16 mma tiles.
// Double-buffered smem (hoisted to wrapper so instantiations share it), one sync/K-tile;
// B packed to half2 at load; conflict-free fragment LDS; 2 CTAs/SM.

__device__ __forceinline__ unsigned pack2(float x, float y) {
    __half2 h = __floats2half2_rn(x, y);
    return *reinterpret_cast<unsigned*>(&h);
}

template<typename T>
__device__ __forceinline__ uint2 loadA4(const T* p);
template<>
__device__ __forceinline__ uint2 loadA4<float>(const float* p) {
    float4 v = *(const float4*)p;
    return make_uint2(pack2(v.x, v.y), pack2(v.z, v.w));
}
template<>
__device__ __forceinline__ uint2 loadA4<__half>(const __half* p) {
    return *(const uint2*)p;
}

template<typename T>
__device__ __forceinline__ void storeC2(T* C, size_t idx, float v0, float v1);
template<>
__device__ __forceinline__ void storeC2<float>(float* C, size_t idx, float v0, float v1) {
    *(float2*)(C + idx) = make_float2(v0, v1);
}
template<>
__device__ __forceinline__ void storeC2<__half>(__half* C, size_t idx, float v0, float v1) {
    *(unsigned*)(C + idx) = pack2(v0, v1);
}

__device__ __forceinline__ void mma_f16(float c[4], const unsigned a[4], const unsigned b[2]) {
    asm volatile(
        "mma.sync.aligned.m16n8k16.row.col.f32.f16.f16.f32 "
        "{%0,%1,%2,%3}, {%4,%5,%6,%7}, {%8,%9}, {%0,%1,%2,%3};"
        : "+f"(c[0]), "+f"(c[1]), "+f"(c[2]), "+f"(c[3])
        : "r"(a[0]), "r"(a[1]), "r"(a[2]), "r"(a[3]), "r"(b[0]), "r"(b[1]));
}

template<typename TIN, typename TOUT>
__device__ __forceinline__
void gemm_core(const TIN* __restrict__ A, const float* __restrict__ Bm,
               const float* __restrict__ bias, TOUT* __restrict__ C,
               unsigned* __restrict__ sAs, unsigned* __restrict__ sBs)
{
    const int tid  = threadIdx.x;
    const int lane = tid & 31;
    const int wid  = tid >> 5;
    const int g    = lane >> 2;
    const int tg   = lane & 3;
    const int warpRow = (wid & 3) * 32;
    const int warpCol = (wid >> 2) * 64;
    const int rowBase = blockIdx.y * 128;
    const int colBase = blockIdx.x * 128;

    const int am  = tid >> 3;
    const int akc = (tid & 7) * 4;
    const int ac2 = (tid & 7) * 2;
    const int bp  = tid >> 5;
    const int bnc = (tid & 31) * 4;

    const TIN*   Ap = A + (size_t)rowBase * KDIM;
    const float* Bp = Bm + colBase;

    uint2    ra[4];
    unsigned rbp[8];

#define GLOAD(kt)                                                                         \
    {                                                                                     \
        _Pragma("unroll")                                                                 \
        for (int i = 0; i < 4; i++)                                                       \
            ra[i] = loadA4<TIN>(Ap + (size_t)(am + 32 * i) * KDIM + (kt) * 32 + akc);     \
        {                                                                                 \
            float4 b0 = *(const float4*)(Bp + (size_t)((kt) * 32 + 2 * bp    ) * NDIM + bnc); \
            float4 b1 = *(const float4*)(Bp + (size_t)((kt) * 32 + 2 * bp + 1) * NDIM + bnc); \
            rbp[0] = pack2(b0.x, b1.x); rbp[1] = pack2(b0.y, b1.y);                       \
            rbp[2] = pack2(b0.z, b1.z); rbp[3] = pack2(b0.w, b1.w);                       \
            float4 b2 = *(const float4*)(Bp + (size_t)((kt) * 32 + 2 * bp + 16) * NDIM + bnc); \
            float4 b3 = *(const float4*)(Bp + (size_t)((kt) * 32 + 2 * bp + 17) * NDIM + bnc); \
            rbp[4] = pack2(b2.x, b3.x); rbp[5] = pack2(b2.y, b3.y);                       \
            rbp[6] = pack2(b2.z, b3.z); rbp[7] = pack2(b2.w, b3.w);                       \
        }                                                                                 \
    }

#define SSTORE(buf)                                                                       \
    {                                                                                     \
        _Pragma("unroll")                                                                 \
        for (int i = 0; i < 4; i++)                                                       \
            *(uint2*)(&sAs[(buf)*AS_BUF + (am + 32 * i)*AS_STRIDE + ac2]) = ra[i];        \
        *(uint4*)(&sBs[(buf)*BS_BUF + bp*BS_STRIDE + bnc])                                \
            = make_uint4(rbp[0], rbp[1], rbp[2], rbp[3]);                                 \
        *(uint4*)(&sBs[(buf)*BS_BUF + (bp + 8)*BS_STRIDE + bnc])                          \
            = make_uint4(rbp[4], rbp[5], rbp[6], rbp[7]);                                 \
    }

    float acc[2][8][4];
#pragma unroll
    for (int mt = 0; mt < 2; mt++)
#pragma unroll
        for (int nt = 0; nt < 8; nt++)
#pragma unroll
            for (int j = 0; j < 4; j++) acc[mt][nt][j] = 0.f;

    GLOAD(0);
    SSTORE(0);
    __syncthreads();

    const int TILES = KDIM / 32;   // 8
#pragma unroll
    for (int kt = 0; kt < TILES; kt++) {
        const int cur = kt & 1;
        if (kt < TILES - 1) GLOAD(kt + 1);

        const unsigned* As = sAs + cur * AS_BUF;
        const unsigned* Bs = sBs + cur * BS_BUF;
#pragma unroll
        for (int s = 0; s < 2; s++) {
            const int kc0 = s * 8;
            unsigned af[2][4];
#pragma unroll
            for (int mt = 0; mt < 2; mt++) {
                const int r0 = warpRow + mt * 16 + g;
                af[mt][0] = As[r0 * AS_STRIDE + kc0 + tg];
                af[mt][1] = As[(r0 + 8) * AS_STRIDE + kc0 + tg];
                af[mt][2] = As[r0 * AS_STRIDE + kc0 + 4 + tg];
                af[mt][3] = As[(r0 + 8) * AS_STRIDE + kc0 + 4 + tg];
            }
            unsigned bf[8][2];
#pragma unroll
            for (int nt = 0; nt < 8; nt++) {
                const int c0 = warpCol + nt * 8 + g;
                bf[nt][0] = Bs[(kc0 + tg) * BS_STRIDE + c0];
                bf[nt][1] = Bs[(kc0 + 4 + tg) * BS_STRIDE + c0];
            }
#pragma unroll
            for (int mt = 0; mt < 2; mt++)
#pragma unroll
                for (int nt = 0; nt < 8; nt++)
                    mma_f16(acc[mt][nt], af[mt], bf[nt]);
        }
        if (kt < TILES - 1) SSTORE(1 - cur);
        __syncthreads();
    }

#pragma unroll
    for (int mt = 0; mt < 2; mt++) {
        const int row = rowBase + warpRow + mt * 16 + g;
#pragma unroll
        for (int nt = 0; nt < 8; nt++) {
            const int col = colBase + warpCol + nt * 8 + tg * 2;
            const float2 bv = *(const float2*)(bias + col);
            storeC2<TOUT>(C, (size_t)row * NDIM + col,
                          acc[mt][nt][0] + bv.x, acc[mt][nt][1] + bv.y);
            storeC2<TOUT>(C, (size_t)(row + 8) * NDIM + col,
                          acc[mt][nt][2] + bv.x, acc[mt][nt][3] + bv.y);
        }
    }
#undef GLOAD
#undef SSTORE
}

__global__ __launch_bounds__(256, 2)
void gemm_heads(const float* __restrict__ query, const float* __restrict__ Weff,
                const float* __restrict__ beff,  float* __restrict__ offA,
                const float* __restrict__ keys0, const float* __restrict__ keys1,
                const float* __restrict__ Wk,    const float* __restrict__ bk,
                __half* __restrict__ sf0h, __half* __restrict__ sf1h)
{
    __shared__ __align__(16) unsigned sAs[2 * AS_BUF];
    __shared__ __align__(16) unsigned sBs[2 * BS_BUF];
    if (blockIdx.z == 0)      gemm_core<float, float >(query, Weff, beff, offA, sAs, sBs);
    else if (blockIdx.z == 1) gemm_core<float, __half>(keys0, Wk, bk, sf0h, sAs, sBs);
    else                      gemm_core<float, __half>(keys1, Wk, bk, sf1h, sAs, sBs);
}

__global__ __launch_bounds__(256, 2)
void gemm_out(const __half* __restrict__ A, const float* __restrict__ Bm,
              const float* __restrict__ bias, float* __restrict__ C)
{
    __shared__ __align__(16) unsigned sAs[2 * AS_BUF];
    __shared__ __align__(16) unsigned sBs[2 * BS_BUF];
    gemm_core<__half, float>(A, Bm, bias, C, sAs, sBs);
}

// ------------------------- deformable sampling: two-phase ----------------------------------
// Block = 4 pixels. Phase 1 (256 thr = 4px x 8h x 8pt): softmax weight + 4 clamped corner
// indices + 4 premultiplied corner weights (0 if OOB). Phase 2 (256 thr = 4px x 8h x 8 lanes):
// each lane gathers uint2 (4 channels) per corner, branch-free.
__global__ __launch_bounds__(256)
void sample_kernel(const float* __restrict__ refp)
{
    __shared__ float s_w [4][NH_][8][4];
    __shared__ int   s_ix[4][NH_][8][4];

    const int blk = blockIdx.x;
    const int tid = threadIdx.x;

    {
        const int j   = tid & 7;          // point
        const int h   = (tid >> 3) & 7;   // head
        const int sub = tid >> 6;         // pixel within block
        const int pixel = blk * 4 + sub;
        const int b = pixel / (H_ * W_);
        const int rem = pixel - b * (H_ * W_);
        // torch .repeat quirk: ref for bh-index n = b*NH+h is ref_point[n % B]
        const int rb = (b * NH_ + h) % B_;
        const float ry = refp[(rb * (H_ * W_) + rem) * 2 + 0];
        const float rx = refp[(rb * (H_ * W_) + rem) * 2 + 1];

        const float lgj = g_offA[(size_t)pixel * NOAP + 128 + h * 8 + j];
        float mx = lgj;
#pragma unroll
        for (int o = 4; o; o >>= 1) mx = fmaxf(mx, __shfl_xor_sync(0xffffffffu, mx, o, 8));
        const float e = expf(lgj - mx);
        float s = e;
#pragma unroll
        for (int o = 4; o; o >>= 1) s += __shfl_xor_sync(0xffffffffu, s, o, 8);
        const float w = e / s;

        const float offy = g_offA[(size_t)pixel * NOAP + h * 16 + j * 2 + 0];
        const float offx = g_offA[(size_t)pixel * NOAP + h * 16 + j * 2 + 1];
        const float py = (ry + offy) * ((float)H_ / (float)(H_ - 1)) - 0.5f;
        const float px = (rx + offx) * ((float)W_ / (float)(W_ - 1)) - 0.5f;
        const float fy = floorf(py), fx = floorf(px);
        const int y0 = (int)fy, x0 = (int)fx;
        const float wy1 = py - fy, wx1 = px - fx;
        const float wy0 = 1.f - wy1, wx0 = 1.f - wx1;
        const bool yv0 = (y0 >= 0) && (y0 < H_);
        const bool yv1 = (y0 + 1 >= 0) && (y0 + 1 < H_);
        const bool xv0 = (x0 >= 0) && (x0 < W_);
        const bool xv1 = (x0 + 1 >= 0) && (x0 + 1 < W_);
        const int y0c = min(max(y0, 0), H_ - 1), y1c = min(max(y0 + 1, 0), H_ - 1);
        const int x0c = min(max(x0, 0), W_ - 1), x1c = min(max(x0 + 1, 0), W_ - 1);
        const int basepix = b * (H_ * W_);
        s_ix[sub][h][j][0] = (basepix + y0c * W_ + x0c) * DM_;
        s_ix[sub][h][j][1] = (basepix + y0c * W_ + x1c) * DM_;
        s_ix[sub][h][j][2] = (basepix + y1c * W_ + x0c) * DM_;
        s_ix[sub][h][j][3] = (basepix + y1c * W_ + x1c) * DM_;
        s_w [sub][h][j][0] = (yv0 && xv0) ? w * wy0 * wx0 : 0.f;
        s_w [sub][h][j][1] = (yv0 && xv1) ? w * wy0 * wx1 : 0.f;
        s_w [sub][h][j][2] = (yv1 && xv0) ? w * wy1 * wx0 : 0.f;
        s_w [sub][h][j][3] = (yv1 && xv1) ? w * wy1 * wx1 : 0.f;
    }
    __syncthreads();

    const int sub = tid >> 6;
    const int h = (tid >> 3) & 7;
    const int e = tid & 7;
    const int pixel = blk * 4 + sub;
    const int chan = h * 32 + e * 4;

    float a0 = 0.f, a1 = 0.f, a2 = 0.f, a3 = 0.f;
#pragma unroll
    for (int l = 0; l < 2; l++) {
        const __half* sf = (l ? g_sf1h : g_sf0h) + chan;
#pragma unroll
        for (int k = 0; k < 4; k++) {
            const int j = l * 4 + k;
            const float4 w4 = *(const float4*)(s_w[sub][h][j]);
            const int4   i4 = *(const int4*)(s_ix[sub][h][j]);
#pragma unroll
            for (int c = 0; c < 4; c++) {
                const int   idx = (&i4.x)[c];
                const float wc  = (&w4.x)[c];
                const uint2 u   = *(const uint2*)(sf + idx);
                const float2 p0 = __half22float2(*(const __half2*)(&u.x));
                const float2 p1 = __half22float2(*(const __half2*)(&u.y));
                a0 += wc * p0.x; a1 += wc * p0.y;
                a2 += wc * p1.x; a3 += wc * p1.y;
            }
        }
    }
    *(uint2*)(g_feath + (size_t)pixel * DM_ + chan) = make_uint2(pack2(a0, a1), pack2(a2, a3));
}

// ------------------------- launch -------------------------
extern "C" void kernel_launch(void* const* d_in, const int* in_sizes, int n_in,
                              void* d_out, int out_size)
{
    const float* query = (const float*)d_in[0];
    const float* keys0 = (const float*)d_in[1];
    const float* keys1 = (const float*)d_in[2];
    const float* refp  = (const float*)d_in[3];
    const float* Wq = (const float*)d_in[4];
    const float* bq = (const float*)d_in[5];
    const float* Wk = (const float*)d_in[6];
    const float* bk = (const float*)d_in[7];
    const float* Wo = (const float*)d_in[8];
    const float* bo = (const float*)d_in[9];
    const float* Wa = (const float*)d_in[10];
    const float* ba = (const float*)d_in[11];
    const float* Wm = (const float*)d_in[12];
    const float* bm = (const float*)d_in[13];
    float* out = (float*)d_out;

    __half *sf0h, *sf1h, *feath;
    float *offA, *Weff, *beff;
    cudaGetSymbolAddress((void**)&sf0h,  g_sf0h);
    cudaGetSymbolAddress((void**)&sf1h,  g_sf1h);
    cudaGetSymbolAddress((void**)&feath, g_feath);
    cudaGetSymbolAddress((void**)&offA,  g_offA);
    cudaGetSymbolAddress((void**)&Weff,  g_Weff);
    cudaGetSymbolAddress((void**)&beff,  g_beff);

    wbeff_kernel<<<DM_ + 1, 256>>>(Wq, Wo, Wa, bq, bo, ba);

    dim3 gh(NDIM / 128, NPIX / 128, 3);    // (2, 256, 3)
    gemm_heads<<<gh, 256>>>(query, Weff, beff, offA, keys0, keys1, Wk, bk, sf0h, sf1h);

    sample_kernel<<<NPIX / 4, 256>>>(refp);

    dim3 gg(NDIM / 128, NPIX / 128);       // (2, 256)
    gemm_out<<<gg, 256>>>(feath, Wm, bm, out);

    (void)in_sizes; (void)n_in; (void)out_size;
}